// round 14
// baseline (speedup 1.0000x reference)
#include <cuda_runtime.h>
#include <math.h>

// Problem shape (fixed by the reference)
#define BB     32
#define CC     256
#define HH     128
#define WW     128
#define HWSZ   (HH * WW)     // 16384
#define HW4    (HWSZ / 4)    // 4096 float4 per (b) spatial plane
#define TPB    128           // 128-thread CTAs (proven granularity)
#define CHUNKS (HW4 / TPB)   // 32 chunk-CTAs per batch plane (8 rows each)
#define PF     2             // x channels prefetched across the barrier

// Scratch (allocation-free: __device__ globals, zero-initialized at load).
__device__ float g_avg[BB * HWSZ];
__device__ float g_max[BB * HWSZ];
// Self-resetting per-batch barrier state (proven R13): the 32nd departing
// CTA resets all three words to 0, so state is identically zero at kernel
// exit on every graph replay. No init kernel, no static guards.
__device__ unsigned int g_arrive[BB];
__device__ unsigned int g_rel[BB];
__device__ unsigned int g_done[BB];

// ---------------------------------------------------------------------------
// Single fused kernel (R13-proven 237.9us @ 83.2% DRAM) + x-prefetch across
// the barrier. grid (32, 32) = 1024 CTAs x 128 thr.
// launch_bounds(128,7): reg cap 72 (room for 2 float4 prefetch regs);
// 148 SMs x 7 slots = 1036 >= 1024 and 72*128*7 = 64512 <= 64K regs, so all
// CTAs remain wave-1 resident -> the barrier spin cannot deadlock.
//
// Phase 1: channel mean+max over this CTA's 128 float4 columns of batch b,
//   unroll 8 (proven read config). Publish avg/max.
// Prefetch: issue LDGs for x channels 0..PF-1 BEFORE the barrier sync; they
//   stream during the straggler wait and the gate FMAs (ptxas front-hoists
//   independent LDGs), hiding the apply ramp-up.
// Phase 2: self-resetting per-batch barrier (proven; keeps chip phase-
//   coherent — R11 measured a 7% DRAM-efficiency loss without it).
// Phase 3: proven gate prologue (3x3x2 correlation, zero pad, sigmoid;
//   conv_w [1,2,3,3] row-major = correlation for NCHW/OIHW), then the
//   unroll-4 apply loop consuming the prefetched channels first.
// ---------------------------------------------------------------------------
__global__ __launch_bounds__(TPB, 7) void fused_attn(const float* __restrict__ x,
                                                     const float* __restrict__ y,
                                                     const float* __restrict__ cw,
                                                     float* __restrict__ out) {
    const int b  = blockIdx.y;
    const int t4 = blockIdx.x * TPB + threadIdx.x;   // float4 index in plane

    // ---- Phase 1: channel reduce for own chunk --------------------------
    {
        const float4* yp = reinterpret_cast<const float4*>(y)
                         + (size_t)b * CC * HW4 + t4;

        float4 s = make_float4(0.f, 0.f, 0.f, 0.f);
        float4 m = make_float4(-INFINITY, -INFINITY, -INFINITY, -INFINITY);

        #pragma unroll 8
        for (int c = 0; c < CC; ++c) {
            float4 v = yp[(size_t)c * HW4];
            s.x += v.x; s.y += v.y; s.z += v.z; s.w += v.w;
            m.x = fmaxf(m.x, v.x); m.y = fmaxf(m.y, v.y);
            m.z = fmaxf(m.z, v.z); m.w = fmaxf(m.w, v.w);
        }

        const float inv = 1.0f / (float)CC;
        float4 a = make_float4(s.x * inv, s.y * inv, s.z * inv, s.w * inv);

        reinterpret_cast<float4*>(g_avg)[(size_t)b * HW4 + t4] = a;
        reinterpret_cast<float4*>(g_max)[(size_t)b * HW4 + t4] = m;
    }

    // ---- Prefetch first PF x channels (independent of the barrier) ------
    const size_t base = (size_t)b * CC * HW4 + t4;
    const float4* xp = reinterpret_cast<const float4*>(x) + base;
    float4*       op = reinterpret_cast<float4*>(out)     + base;

    float4 pf[PF];
    #pragma unroll
    for (int u = 0; u < PF; ++u)
        pf[u] = xp[(size_t)u * HW4];           // LDGs in flight across barrier

    // ---- Phase 2: self-resetting per-batch barrier ----------------------
    __syncthreads();                           // all CTA stores issued
    if (threadIdx.x == 0) {
        __threadfence();                       // release: publish avg/max
        unsigned prev = atomicAdd(&g_arrive[b], 1u);
        if (prev == (unsigned)(CHUNKS - 1))
            atomicExch(&g_rel[b], 1u);         // last arriver releases batch
        while (atomicAdd(&g_rel[b], 0u) == 0u)
            __nanosleep(100);
        __threadfence();                       // acquire: see peers' avg/max
        unsigned fin = atomicAdd(&g_done[b], 1u);
        if (fin == (unsigned)(CHUNKS - 1)) {   // last departer resets state
            atomicExch(&g_arrive[b], 0u);
            atomicExch(&g_done[b],   0u);
            atomicExch(&g_rel[b],    0u);
        }
    }
    __syncthreads();

    // ---- Phase 3a: gate prologue ----------------------------------------
    const int p0 = t4 * 4;                     // first pixel index
    const int h  = p0 >> 7;                    // row (4 px share a row)
    const int w0 = p0 & (WW - 1);              // first col (0..124)

    float wt[18];
    #pragma unroll
    for (int i = 0; i < 18; ++i) wt[i] = __ldg(&cw[i]);

    float A[3][6], M[3][6];
    #pragma unroll
    for (int r = 0; r < 3; ++r) {
        const int hh = h - 1 + r;
        const bool hv = (hh >= 0) && (hh < HH);
        #pragma unroll
        for (int cc = 0; cc < 6; ++cc) {
            const int ww = w0 - 1 + cc;
            const bool v = hv && (ww >= 0) && (ww < WW);
            const int off = b * HWSZ + hh * WW + ww;
            A[r][cc] = v ? g_avg[off] : 0.0f;
            M[r][cc] = v ? g_max[off] : 0.0f;
        }
    }

    float4 g;
    float* gp = &g.x;
    #pragma unroll
    for (int i = 0; i < 4; ++i) {
        float acc = 0.0f;
        #pragma unroll
        for (int r = 0; r < 3; ++r) {
            #pragma unroll
            for (int dj = 0; dj < 3; ++dj) {
                const int k = r * 3 + dj;
                acc = fmaf(A[r][i + dj], wt[k],     acc);
                acc = fmaf(M[r][i + dj], wt[9 + k], acc);
            }
        }
        gp[i] = 1.0f / (1.0f + expf(-acc));
    }

    // ---- Phase 3b: consume prefetched channels, then main loop ----------
    #pragma unroll
    for (int u = 0; u < PF; ++u) {
        float4 v = pf[u];
        v.x *= g.x; v.y *= g.y; v.z *= g.z; v.w *= g.w;
        op[(size_t)u * HW4] = v;
    }

    #pragma unroll 4
    for (int c = PF; c < CC; ++c) {
        float4 v = xp[(size_t)c * HW4];
        v.x *= g.x; v.y *= g.y; v.z *= g.z; v.w *= g.w;
        op[(size_t)c * HW4] = v;
    }
}

// ---------------------------------------------------------------------------
// Launch. Inputs (metadata order): d_in[0]=x [B,C,H,W] f32,
// d_in[1]=y [B,C,H,W] f32, d_in[2]=conv_w [1,2,3,3] f32. Output f32 [B,C,H,W].
// ---------------------------------------------------------------------------
extern "C" void kernel_launch(void* const* d_in, const int* in_sizes, int n_in,
                              void* d_out, int out_size) {
    (void)in_sizes; (void)n_in; (void)out_size;
    const float* x  = (const float*)d_in[0];
    const float* y  = (const float*)d_in[1];
    const float* cw = (const float*)d_in[2];
    float* out = (float*)d_out;

    dim3 grid(CHUNKS, BB);               // (32, 32) = 1024 CTAs of 128 thr
    fused_attn<<<grid, TPB>>>(x, y, cw, out);
}

// round 16
// speedup vs baseline: 1.0294x; 1.0294x over previous
#include <cuda_runtime.h>
#include <math.h>

// Problem shape (fixed by the reference)
#define BB     32
#define CC     256
#define HH     128
#define WW     128
#define HWSZ   (HH * WW)     // 16384
#define HW4    (HWSZ / 4)    // 4096 float4 per (b) spatial plane
#define TPB    128           // 128-thread CTAs (R9-proven granularity)
#define CHUNKS (HW4 / TPB)   // 32 chunk-CTAs per batch plane (8 rows each)

// Scratch (allocation-free: __device__ globals, zero-initialized at load).
__device__ float g_avg[BB * HWSZ];
__device__ float g_max[BB * HWSZ];
// Self-resetting per-batch barrier state. The 32nd departing CTA resets all
// three words to 0, so state is identically zero at kernel exit on every
// graph replay (deterministic; no init kernel, no static guards).
__device__ unsigned int g_arrive[BB];
__device__ unsigned int g_rel[BB];
__device__ unsigned int g_done[BB];

// ---------------------------------------------------------------------------
// Single fused kernel — SESSION BEST (R13: 252.7us total, kernel 237.9us @
// 83.2% DRAM): reduce -> self-resetting per-batch barrier -> conv gate ->
// apply, one graph node. grid (32, 32) = 1024 CTAs x 128 thr, ALL wave-1
// resident (148 SMs x 7 CTA slots = 1036; launch_bounds(128,8) caps regs at
// 64 — measured optimal, cap 72 in R14 regressed 10us), so the barrier spin
// cannot deadlock.
//
// Phase 1: channel mean+max over this CTA's 128 float4 columns (8 rows) of
//   batch b, unroll 8 (proven read config: 86% DRAM standalone). Publish.
// Phase 2: per-batch barrier — keeps the chip phase-coherent (R11 measured
//   7% DRAM-efficiency loss without it). Self-resetting: arrive-count ->
//   last sets release; all poll release; depart-count -> last resets state.
// Phase 3: gate prologue (3x3x2 correlation, zero pad, sigmoid; conv_w
//   [1,2,3,3] row-major = correlation for NCHW/OIHW) + unroll-4 apply loop
//   (unroll 4 proven best MLP for the mixed R/W stream: 8 regressed, R7).
// ---------------------------------------------------------------------------
__global__ __launch_bounds__(TPB, 8) void fused_attn(const float* __restrict__ x,
                                                     const float* __restrict__ y,
                                                     const float* __restrict__ cw,
                                                     float* __restrict__ out) {
    const int b  = blockIdx.y;
    const int t4 = blockIdx.x * TPB + threadIdx.x;   // float4 index in plane

    // ---- Phase 1: channel reduce for own chunk --------------------------
    {
        const float4* yp = reinterpret_cast<const float4*>(y)
                         + (size_t)b * CC * HW4 + t4;

        float4 s = make_float4(0.f, 0.f, 0.f, 0.f);
        float4 m = make_float4(-INFINITY, -INFINITY, -INFINITY, -INFINITY);

        #pragma unroll 8
        for (int c = 0; c < CC; ++c) {
            float4 v = yp[(size_t)c * HW4];
            s.x += v.x; s.y += v.y; s.z += v.z; s.w += v.w;
            m.x = fmaxf(m.x, v.x); m.y = fmaxf(m.y, v.y);
            m.z = fmaxf(m.z, v.z); m.w = fmaxf(m.w, v.w);
        }

        const float inv = 1.0f / (float)CC;
        float4 a = make_float4(s.x * inv, s.y * inv, s.z * inv, s.w * inv);

        reinterpret_cast<float4*>(g_avg)[(size_t)b * HW4 + t4] = a;
        reinterpret_cast<float4*>(g_max)[(size_t)b * HW4 + t4] = m;
    }

    // ---- Phase 2: self-resetting per-batch barrier ----------------------
    __syncthreads();                           // all CTA stores issued
    if (threadIdx.x == 0) {
        __threadfence();                       // release: publish avg/max
        unsigned prev = atomicAdd(&g_arrive[b], 1u);
        if (prev == (unsigned)(CHUNKS - 1))
            atomicExch(&g_rel[b], 1u);         // last arriver releases batch
        while (atomicAdd(&g_rel[b], 0u) == 0u)
            __nanosleep(100);
        __threadfence();                       // acquire: see peers' avg/max
        unsigned fin = atomicAdd(&g_done[b], 1u);
        if (fin == (unsigned)(CHUNKS - 1)) {   // last departer resets state
            atomicExch(&g_arrive[b], 0u);
            atomicExch(&g_done[b],   0u);
            atomicExch(&g_rel[b],    0u);
        }
    }
    __syncthreads();

    // ---- Phase 3a: gate prologue ----------------------------------------
    const int p0 = t4 * 4;                     // first pixel index
    const int h  = p0 >> 7;                    // row (4 px share a row)
    const int w0 = p0 & (WW - 1);              // first col (0..124)

    float wt[18];
    #pragma unroll
    for (int i = 0; i < 18; ++i) wt[i] = __ldg(&cw[i]);

    float A[3][6], M[3][6];
    #pragma unroll
    for (int r = 0; r < 3; ++r) {
        const int hh = h - 1 + r;
        const bool hv = (hh >= 0) && (hh < HH);
        #pragma unroll
        for (int cc = 0; cc < 6; ++cc) {
            const int ww = w0 - 1 + cc;
            const bool v = hv && (ww >= 0) && (ww < WW);
            const int off = b * HWSZ + hh * WW + ww;
            A[r][cc] = v ? g_avg[off] : 0.0f;
            M[r][cc] = v ? g_max[off] : 0.0f;
        }
    }

    float4 g;
    float* gp = &g.x;
    #pragma unroll
    for (int i = 0; i < 4; ++i) {
        float acc = 0.0f;
        #pragma unroll
        for (int r = 0; r < 3; ++r) {
            #pragma unroll
            for (int dj = 0; dj < 3; ++dj) {
                const int k = r * 3 + dj;
                acc = fmaf(A[r][i + dj], wt[k],     acc);
                acc = fmaf(M[r][i + dj], wt[9 + k], acc);
            }
        }
        gp[i] = 1.0f / (1.0f + expf(-acc));
    }

    // ---- Phase 3b: apply main loop (unroll 4, proven best) --------------
    const size_t base = (size_t)b * CC * HW4 + t4;
    const float4* xp = reinterpret_cast<const float4*>(x) + base;
    float4*       op = reinterpret_cast<float4*>(out)     + base;

    #pragma unroll 4
    for (int c = 0; c < CC; ++c) {
        float4 v = xp[(size_t)c * HW4];
        v.x *= g.x; v.y *= g.y; v.z *= g.z; v.w *= g.w;
        op[(size_t)c * HW4] = v;
    }
}

// ---------------------------------------------------------------------------
// Launch. Inputs (metadata order): d_in[0]=x [B,C,H,W] f32,
// d_in[1]=y [B,C,H,W] f32, d_in[2]=conv_w [1,2,3,3] f32. Output f32 [B,C,H,W].
// ---------------------------------------------------------------------------
extern "C" void kernel_launch(void* const* d_in, const int* in_sizes, int n_in,
                              void* d_out, int out_size) {
    (void)in_sizes; (void)n_in; (void)out_size;
    const float* x  = (const float*)d_in[0];
    const float* y  = (const float*)d_in[1];
    const float* cw = (const float*)d_in[2];
    float* out = (float*)d_out;

    dim3 grid(CHUNKS, BB);               // (32, 32) = 1024 CTAs of 128 thr
    fused_attn<<<grid, TPB>>>(x, y, cw, out);
}